// round 4
// baseline (speedup 1.0000x reference)
#include <cuda_runtime.h>

#define N_ANCH   1000
#define N_FEAT   78
#define NTHREADS 256
#define N_TASKS  1024
#define K_MAX    64

// Per-task partial results: {sl1l, ll, fl} per (image,lane)
__device__ float g_part[N_TASKS * 3];

__device__ __forceinline__ unsigned fkey(float f) {
    unsigned u = __float_as_uint(f);
    return (u & 0x80000000u) ? ~u : (u | 0x80000000u);
}

__global__ __launch_bounds__(NTHREADS)
void lane_kernel(const float* __restrict__ output, const float* __restrict__ label)
{
    __shared__ float  sp[N_FEAT];     // prior
    __shared__ float  A[N_ANCH];      // product -> cost
    __shared__ float  B[N_ANCH];      // focal
    __shared__ float4 red[NTHREADS];  // reduction scratch
    __shared__ int    hist[256];
    __shared__ int    sel[K_MAX];
    __shared__ int    si2[2];
    __shared__ int    scan_s[NTHREADS];

    const int task = blockIdx.x;
    const int img  = task >> 4;
    const float* feat  = output + (size_t)img * N_ANCH * N_FEAT;
    const float* prior = label  + (size_t)task * N_FEAT;
    const int tid = threadIdx.x;

    for (int j = tid; j < N_FEAT; j += NTHREADS) sp[j] = prior[j];
    __syncthreads();

    // ---------------- Phase A: log-softmax over anchors (axis=0) for cols 0,1
    float m0 = -1e30f, m1 = -1e30f;
    for (int i = tid; i < N_ANCH; i += NTHREADS) {
        float2 v = *(const float2*)(feat + i * N_FEAT);
        m0 = fmaxf(m0, v.x); m1 = fmaxf(m1, v.y);
    }
    red[tid] = make_float4(m0, m1, 0.f, 0.f);
    __syncthreads();
    for (int s = NTHREADS / 2; s > 0; s >>= 1) {
        if (tid < s) {
            red[tid].x = fmaxf(red[tid].x, red[tid + s].x);
            red[tid].y = fmaxf(red[tid].y, red[tid + s].y);
        }
        __syncthreads();
    }
    const float M0 = red[0].x, M1 = red[0].y;
    __syncthreads();

    float s0 = 0.f, s1 = 0.f;
    for (int i = tid; i < N_ANCH; i += NTHREADS) {
        float2 v = *(const float2*)(feat + i * N_FEAT);
        s0 += expf(v.x - M0); s1 += expf(v.y - M1);
    }
    red[tid] = make_float4(s0, s1, 0.f, 0.f);
    __syncthreads();
    for (int s = NTHREADS / 2; s > 0; s >>= 1) {
        if (tid < s) {
            red[tid].x += red[tid + s].x;
            red[tid].y += red[tid + s].y;
        }
        __syncthreads();
    }
    const float lse0 = M0 + logf(red[0].x);
    const float lse1 = M1 + logf(red[0].y);
    __syncthreads();

    // ---------------- Phase B: per-anchor cost pieces
    const float p0 = sp[0], p1 = sp[1];
    const float px = sp[3], py = sp[4], pth = sp[5];
    float sxy = 0.f, sth = 0.f, sdis = 0.f, sliou = 0.f;
    for (int i = tid; i < N_ANCH; i += NTHREADS) {
        const float2* r = (const float2*)(feat + i * N_FEAT);
        float2 v0 = r[0], v1 = r[1], v2 = r[2];
        float ls0 = v0.x - lse0, ls1 = v0.y - lse1;
        float e0 = expf(ls0), e1 = expf(ls1);
        float focal = (1.f - e0) * (1.f - e0) * ls0 * p0
                    + (1.f - e1) * (1.f - e1) * ls1 * p1;
        float dx = v1.y - px, dy = v2.x - py;
        float xy = sqrtf(dx * dx + dy * dy);
        float th = v2.y - pth;
        float L1 = 0.f;
        #pragma unroll 12
        for (int j = 3; j < 39; ++j) {
            float2 v = r[j];
            L1 += fabsf(v.x - sp[2 * j]) + fabsf(v.y - sp[2 * j + 1]);
        }
        float dis  = L1 * (1.0f / 72.0f);
        float liou = 1.f - (2160.f - L1) / (2160.f + L1 + 1e-9f);
        A[i] = dis * xy * th;
        B[i] = focal;
        sxy += xy * xy; sth += th * th; sdis += dis * dis; sliou += liou;
    }
    red[tid] = make_float4(sxy, sth, sdis, sliou);
    __syncthreads();
    for (int s = NTHREADS / 2; s > 0; s >>= 1) {
        if (tid < s) {
            float4 a = red[tid], b = red[tid + s];
            red[tid] = make_float4(a.x + b.x, a.y + b.y, a.z + b.z, a.w + b.w);
        }
        __syncthreads();
    }
    const float4 tot = red[0];
    __syncthreads();

    const float Nx = fmaxf(sqrtf(tot.x), 1e-12f);
    const float Nt = fmaxf(sqrtf(tot.y), 1e-12f);
    const float Nd = fmaxf(sqrtf(tot.z), 1e-12f);
    const float invn = 1.f / (Nx * Nt * Nd);
    int k = (int)tot.w;
    if (k < 1) k = 1;
    if (k > K_MAX) k = K_MAX;

    // ---------------- Phase C: finalize cost
    for (int i = tid; i < N_ANCH; i += NTHREADS) {
        float t = A[i] * invn;
        A[i] = 3.0f * t * t + 1.0f * B[i];
    }
    __syncthreads();

    // ---------------- Phase D: radix-select k-th smallest cost key
    unsigned prefix = 0; int kk = k;
    for (int shift = 24; shift >= 0; shift -= 8) {
        hist[tid] = 0;
        __syncthreads();
        unsigned pmask = (shift == 24) ? 0u : (0xFFFFFFFFu << (shift + 8));
        for (int i = tid; i < N_ANCH; i += NTHREADS) {
            unsigned key = fkey(A[i]);
            if ((key & pmask) == prefix) atomicAdd(&hist[(key >> shift) & 255], 1);
        }
        __syncthreads();
        if (tid == 0) {
            int cum = 0, b2 = 0;
            for (; b2 < 256; ++b2) {
                int c = hist[b2];
                if (cum + c >= kk) break;
                cum += c;
            }
            si2[0] = b2; si2[1] = kk - cum;
        }
        __syncthreads();
        prefix |= ((unsigned)si2[0]) << shift;
        kk = si2[1];
        __syncthreads();
    }
    const unsigned T = prefix;
    const int      rties = kk;   // need first rties ties (by index) at value T

    // ---------------- Phase E: deterministic compaction of selected indices
    int cnt = 0;
    for (int i = tid; i < N_ANCH; i += NTHREADS) {
        unsigned key = fkey(A[i]);
        bool pick = key < T;
        if (key == T) {
            int tr = 0;
            for (int j = 0; j < i; ++j) if (fkey(A[j]) == T) ++tr;
            pick = (tr < rties);
        }
        if (pick) ++cnt;
    }
    scan_s[tid] = cnt;
    __syncthreads();
    for (int s = 1; s < NTHREADS; s <<= 1) {
        int v = (tid >= s) ? scan_s[tid - s] : 0;
        __syncthreads();
        scan_s[tid] += v;
        __syncthreads();
    }
    int o = scan_s[tid] - cnt;
    for (int i = tid; i < N_ANCH; i += NTHREADS) {
        unsigned key = fkey(A[i]);
        bool pick = key < T;
        if (key == T) {
            int tr = 0;
            for (int j = 0; j < i; ++j) if (fkey(A[j]) == T) ++tr;
            pick = (tr < rties);
        }
        if (pick) sel[o++] = i;
    }
    __syncthreads();

    // ---------------- Stage 2, pass 1: colnorm squares over cols 2..5
    float q2 = 0.f, q3 = 0.f, q4 = 0.f, q5 = 0.f;
    if (tid < k) {
        const float* row = feat + (size_t)sel[tid] * N_FEAT;
        float a = row[2], b = row[3], c = row[4], d = row[5];
        q2 = a * a; q3 = b * b; q4 = c * c; q5 = d * d;
    }
    red[tid] = make_float4(q2, q3, q4, q5);
    __syncthreads();
    for (int s = NTHREADS / 2; s > 0; s >>= 1) {
        if (tid < s) {
            float4 a = red[tid], b = red[tid + s];
            red[tid] = make_float4(a.x + b.x, a.y + b.y, a.z + b.z, a.w + b.w);
        }
        __syncthreads();
    }
    const float4 qs = red[0];
    __syncthreads();
    const float den2 = fmaxf(sqrtf(qs.x + sp[2] * sp[2]), 1e-12f);
    const float den3 = fmaxf(sqrtf(qs.y + sp[3] * sp[3]), 1e-12f);
    const float den4 = fmaxf(sqrtf(qs.z + sp[4] * sp[4]), 1e-12f);
    const float den5 = fmaxf(sqrtf(qs.w + sp[5] * sp[5]), 1e-12f);

    // ---------------- Stage 2, pass 2: sl1 / focal / liou over selected rows
    float lsl1 = 0.f, lfl = 0.f, lll = 0.f;
    const int tgt = (sp[1] > sp[0]) ? 1 : 0;
    if (tid < k) {
        const float* row = feat + (size_t)sel[tid] * N_FEAT;
        // smooth-L1 over normalized cols 2..5
        float sacc = 0.f;
        {
            float dd, ad;
            dd = row[2] / den2 - sp[2] / den2; ad = fabsf(dd);
            sacc += (ad < 1.f) ? 0.5f * dd * dd : ad - 0.5f;
            dd = row[3] / den3 - sp[3] / den3; ad = fabsf(dd);
            sacc += (ad < 1.f) ? 0.5f * dd * dd : ad - 0.5f;
            dd = row[4] / den4 - sp[4] / den4; ad = fabsf(dd);
            sacc += (ad < 1.f) ? 0.5f * dd * dd : ad - 0.5f;
            dd = row[5] / den5 - sp[5] / den5; ad = fabsf(dd);
            sacc += (ad < 1.f) ? 0.5f * dd * dd : ad - 0.5f;
        }
        lsl1 = sacc * 0.25f;
        // focal on row logits
        float x0 = row[0], x1 = row[1];
        float mx = fmaxf(x0, x1);
        float lse = mx + logf(expf(x0 - mx) + expf(x1 - mx));
        float logpt = (tgt ? x1 : x0) - lse;
        float pt = expf(logpt);
        lfl = -(1.f - pt) * (1.f - pt) * logpt;
        // liou via L1
        float L1 = 0.f;
        #pragma unroll 12
        for (int j = 6; j < 78; ++j) L1 += fabsf(row[j] - sp[j]);
        lll = 1.f - (2160.f - L1) / (2160.f + L1 + 1e-9f);
    }
    red[tid] = make_float4(lsl1, lll, lfl, 0.f);
    __syncthreads();
    for (int s = NTHREADS / 2; s > 0; s >>= 1) {
        if (tid < s) {
            float4 a = red[tid], b = red[tid + s];
            red[tid] = make_float4(a.x + b.x, a.y + b.y, a.z + b.z, 0.f);
        }
        __syncthreads();
    }
    if (tid == 0) {
        float invk = 1.f / (float)k;
        g_part[task * 3 + 0] = red[0].x * invk;  // sl1l
        g_part[task * 3 + 1] = red[0].y * invk;  // ll
        g_part[task * 3 + 2] = red[0].z * invk;  // fl
    }
}

__global__ __launch_bounds__(NTHREADS)
void finalize_kernel(float* __restrict__ out)
{
    __shared__ float4 red[NTHREADS];
    const int tid = threadIdx.x;
    float a = 0.f, b = 0.f, c = 0.f;
    for (int i = tid; i < N_TASKS; i += NTHREADS) {
        a += g_part[i * 3 + 0];
        b += g_part[i * 3 + 1];
        c += g_part[i * 3 + 2];
    }
    red[tid] = make_float4(a, b, c, 0.f);
    __syncthreads();
    for (int s = NTHREADS / 2; s > 0; s >>= 1) {
        if (tid < s) {
            float4 x = red[tid], y = red[tid + s];
            red[tid] = make_float4(x.x + y.x, x.y + y.y, x.z + y.z, 0.f);
        }
        __syncthreads();
    }
    if (tid == 0) {
        const float inv = 1.f / (float)N_TASKS;
        float sl1l = red[0].x * inv;
        float ll   = red[0].y * inv;
        float fl   = red[0].z * inv;
        float loss = (sl1l > 0.f ? 0.5f * sl1l : 0.f)
                   + (ll   > 0.f ? 2.0f * ll   : 0.f)
                   + (fl   > 0.f ? 2.0f * fl   : 0.f);
        out[0] = loss;
    }
}

extern "C" void kernel_launch(void* const* d_in, const int* in_sizes, int n_in,
                              void* d_out, int out_size)
{
    const float* output = (const float*)d_in[0];  // [64,1000,78]
    const float* label  = (const float*)d_in[1];  // [64,16,78]
    lane_kernel<<<N_TASKS, NTHREADS>>>(output, label);
    finalize_kernel<<<1, NTHREADS>>>((float*)d_out);
}

// round 5
// speedup vs baseline: 1.1613x; 1.1613x over previous
#include <cuda_runtime.h>

#define N_ANCH 1000
#define N_FEAT 78
#define NT     256
#define LPC    4            // lanes per CTA
#define NCTA   256          // 64 images * 4 CTAs
#define K_MAX  64
#define TILE   256
#define TSTR   81           // smem row stride (conflict-free: gcd(81,32)=1)
#define SPSTR  80

#define DYN_FLOATS (TILE*TSTR + 2*N_ANCH + LPC*N_ANCH + LPC*SPSTR)

__device__ float    g_part[1024 * 3];
__device__ unsigned g_ctr;

__device__ __forceinline__ unsigned fkey(float f) {
    unsigned u = __float_as_uint(f);
    return (u & 0x80000000u) ? ~u : (u | 0x80000000u);
}
__device__ __forceinline__ float wsum(float v) {
    #pragma unroll
    for (int o = 16; o; o >>= 1) v += __shfl_xor_sync(0xffffffffu, v, o);
    return v;
}
__device__ __forceinline__ float wmax(float v) {
    #pragma unroll
    for (int o = 16; o; o >>= 1) v = fmaxf(v, __shfl_xor_sync(0xffffffffu, v, o));
    return v;
}
__device__ __forceinline__ int wscan_incl(int v, int lane) {
    #pragma unroll
    for (int o = 1; o < 32; o <<= 1) {
        int t = __shfl_up_sync(0xffffffffu, v, o);
        if (lane >= o) v += t;
    }
    return v;
}

__global__ __launch_bounds__(NT, 2)
void lane_kernel(const float* __restrict__ output, const float* __restrict__ label,
                 float* __restrict__ out)
{
    extern __shared__ float dyn[];
    float* tile = dyn;                       // TILE*TSTR
    float* c0s  = tile + TILE * TSTR;        // 1000 (logits col0 -> focal f0)
    float* c1s  = c0s + N_ANCH;              // 1000
    float* Aarr = c1s + N_ANCH;              // LPC*1000
    float* sp   = Aarr + LPC * N_ANCH;       // LPC*80 priors

    __shared__ float    wred[18 * 8];
    __shared__ int      iw[8];
    __shared__ int      hist[256];
    __shared__ int      sel[K_MAX];
    __shared__ int      si2[2];
    __shared__ float    bres[18];
    __shared__ float    bres2[4];
    __shared__ unsigned sAm;

    const int tid  = threadIdx.x;
    const int wid  = tid >> 5;
    const int lane = tid & 31;
    const int bx   = blockIdx.x;
    const int img  = bx >> 2;
    const int lane0 = (bx & 3) * LPC;
    const float* feat = output + (size_t)img * (N_ANCH * N_FEAT);

    // load 4 priors
    for (int idx = tid; idx < LPC * N_FEAT; idx += NT) {
        int l = idx / N_FEAT, j = idx - l * N_FEAT;
        sp[l * SPSTR + j] = label[((size_t)img * 16 + lane0 + l) * N_FEAT + j];
    }

    float m0 = -3.4e38f, m1 = -3.4e38f;
    float acc[16];
    #pragma unroll
    for (int q = 0; q < 16; ++q) acc[q] = 0.f;

    // ---------------- main pass: tiled, coalesced, 4 lanes share each row
    for (int t = 0; t < 4; ++t) {
        const int base = t * TILE;
        const int cnt  = (N_ANCH - base < TILE) ? (N_ANCH - base) : TILE;
        __syncthreads();                       // tile reuse guard
        const int nf = cnt * N_FEAT;
        const float* g = feat + base * N_FEAT;
        for (int idx = tid; idx < nf; idx += NT) {
            int r = idx / N_FEAT, c = idx - r * N_FEAT;
            tile[r * TSTR + c] = g[idx];
        }
        __syncthreads();
        if (tid < cnt) {
            const float* row = tile + tid * TSTR;
            const int i = base + tid;
            float v0 = row[0], v1 = row[1];
            c0s[i] = v0; c1s[i] = v1;
            m0 = fmaxf(m0, v0); m1 = fmaxf(m1, v1);
            float rx = row[3], ry = row[4], rt = row[5];
            float La = 0.f, Lb = 0.f, Lc = 0.f, Ld = 0.f;
            #pragma unroll 12
            for (int j = 6; j < 78; ++j) {
                float v = row[j];
                La += fabsf(v - sp[0 * SPSTR + j]);
                Lb += fabsf(v - sp[1 * SPSTR + j]);
                Lc += fabsf(v - sp[2 * SPSTR + j]);
                Ld += fabsf(v - sp[3 * SPSTR + j]);
            }
            float Ls[4] = {La, Lb, Lc, Ld};
            #pragma unroll
            for (int l = 0; l < LPC; ++l) {
                float dx = rx - sp[l * SPSTR + 3];
                float dy = ry - sp[l * SPSTR + 4];
                float xy = sqrtf(dx * dx + dy * dy);
                float th = rt - sp[l * SPSTR + 5];
                float L  = Ls[l];
                float dis  = L * (1.0f / 72.0f);
                float liou = 1.f - (2160.f - L) / (2160.f + L + 1e-9f);
                Aarr[l * N_ANCH + i] = dis * xy * th;
                acc[l * 4 + 0] += xy * xy;
                acc[l * 4 + 1] += th * th;
                acc[l * 4 + 2] += dis * dis;
                acc[l * 4 + 3] += liou;
            }
        }
    }

    // ---------------- block-reduce 18 quantities (2 max, 16 sum)
    {
        float v;
        v = wmax(m0); if (lane == 0) wred[0 * 8 + wid] = v;
        v = wmax(m1); if (lane == 0) wred[1 * 8 + wid] = v;
        #pragma unroll
        for (int q = 0; q < 16; ++q) {
            v = wsum(acc[q]); if (lane == 0) wred[(2 + q) * 8 + wid] = v;
        }
        __syncthreads();
        if (tid < 18) {
            float r = wred[tid * 8];
            if (tid < 2) { for (int w = 1; w < 8; ++w) r = fmaxf(r, wred[tid * 8 + w]); }
            else         { for (int w = 1; w < 8; ++w) r += wred[tid * 8 + w]; }
            bres[tid] = r;
        }
        __syncthreads();
    }
    const float M0 = bres[0], M1 = bres[1];

    // ---------------- softmax sums (over smem logits, no gmem)
    float s0 = 0.f, s1 = 0.f;
    for (int i = tid; i < N_ANCH; i += NT) {
        s0 += expf(c0s[i] - M0);
        s1 += expf(c1s[i] - M1);
    }
    {
        float v;
        v = wsum(s0); if (lane == 0) wred[0 * 8 + wid] = v;
        v = wsum(s1); if (lane == 0) wred[1 * 8 + wid] = v;
        __syncthreads();
        if (tid < 2) {
            float r = 0.f;
            for (int w = 0; w < 8; ++w) r += wred[tid * 8 + w];
            bres[tid] = r;   // safe: everyone captured M0/M1 in regs already
        }
        __syncthreads();
    }
    const float lse0 = M0 + logf(bres[0]);
    const float lse1 = M1 + logf(bres[1]);

    // focal factors (feature-only), overwrite logit arrays
    for (int i = tid; i < N_ANCH; i += NT) {
        float ls0 = c0s[i] - lse0, e0 = expf(ls0);
        c0s[i] = (1.f - e0) * (1.f - e0) * ls0;
        float ls1 = c1s[i] - lse1, e1 = expf(ls1);
        c1s[i] = (1.f - e1) * (1.f - e1) * ls1;
    }
    __syncthreads();

    // ---------------- per-lane: cost finalize, radix-select, stage-2
    for (int l = 0; l < LPC; ++l) {
        const float sxy   = bres[2 + l * 4 + 0];
        const float sth   = bres[2 + l * 4 + 1];
        const float sdis  = bres[2 + l * 4 + 2];
        const float sliou = bres[2 + l * 4 + 3];
        const float Nx = fmaxf(sqrtf(sxy),  1e-12f);
        const float Nt2 = fmaxf(sqrtf(sth), 1e-12f);
        const float Nd = fmaxf(sqrtf(sdis), 1e-12f);
        const float invn = 1.f / (Nx * Nt2 * Nd);
        int k = (int)sliou;
        if (k < 1) k = 1;
        if (k > K_MAX) k = K_MAX;
        const float p0 = sp[l * SPSTR + 0], p1 = sp[l * SPSTR + 1];
        float* A = Aarr + l * N_ANCH;

        for (int i = tid; i < N_ANCH; i += NT) {
            float tq = A[i] * invn;
            A[i] = 3.f * tq * tq + p0 * c0s[i] + p1 * c1s[i];
        }
        __syncthreads();

        // radix-select k-th smallest (4x8-bit, parallel hist scan)
        unsigned prefix = 0; int kk = k;
        for (int shift = 24; shift >= 0; shift -= 8) {
            hist[tid] = 0;
            __syncthreads();
            unsigned pmask = (shift == 24) ? 0u : (0xFFFFFFFFu << (shift + 8));
            for (int i = tid; i < N_ANCH; i += NT) {
                unsigned key = fkey(A[i]);
                if ((key & pmask) == prefix) atomicAdd(&hist[(key >> shift) & 255], 1);
            }
            __syncthreads();
            int c = hist[tid];
            int inc = wscan_incl(c, lane);
            if (lane == 31) iw[wid] = inc;
            __syncthreads();
            int off = 0;
            #pragma unroll
            for (int w = 0; w < 8; ++w) if (w < wid) off += iw[w];
            int incl = inc + off;
            if (incl >= kk && incl - c < kk) { si2[0] = tid; si2[1] = kk - (incl - c); }
            __syncthreads();
            prefix |= ((unsigned)si2[0]) << shift;
            kk = si2[1];
            __syncthreads();
        }
        const unsigned T = prefix;
        const int rties = kk;

        // deterministic compaction
        int cnt = 0;
        for (int i = tid; i < N_ANCH; i += NT) {
            unsigned key = fkey(A[i]);
            bool pick = key < T;
            if (key == T) {
                int tr = 0;
                for (int j = 0; j < i; ++j) if (fkey(A[j]) == T) ++tr;
                pick = (tr < rties);
            }
            if (pick) ++cnt;
        }
        {
            int inc = wscan_incl(cnt, lane);
            if (lane == 31) iw[wid] = inc;
            __syncthreads();
            int off = 0;
            #pragma unroll
            for (int w = 0; w < 8; ++w) if (w < wid) off += iw[w];
            int o = off + inc - cnt;
            for (int i = tid; i < N_ANCH; i += NT) {
                unsigned key = fkey(A[i]);
                bool pick = key < T;
                if (key == T) {
                    int tr = 0;
                    for (int j = 0; j < i; ++j) if (fkey(A[j]) == T) ++tr;
                    pick = (tr < rties);
                }
                if (pick) sel[o++] = i;
            }
        }
        __syncthreads();

        // stage-2 pass 1: colnorm squares over cols 2..5
        float q2 = 0.f, q3 = 0.f, q4 = 0.f, q5 = 0.f;
        if (tid < k) {
            const float* row = feat + (size_t)sel[tid] * N_FEAT;
            float a = row[2], b = row[3], c2 = row[4], d = row[5];
            q2 = a * a; q3 = b * b; q4 = c2 * c2; q5 = d * d;
        }
        {
            float v;
            v = wsum(q2); if (lane == 0) wred[0 * 8 + wid] = v;
            v = wsum(q3); if (lane == 0) wred[1 * 8 + wid] = v;
            v = wsum(q4); if (lane == 0) wred[2 * 8 + wid] = v;
            v = wsum(q5); if (lane == 0) wred[3 * 8 + wid] = v;
            __syncthreads();
            if (tid < 4) {
                float r = 0.f;
                for (int w = 0; w < 8; ++w) r += wred[tid * 8 + w];
                bres2[tid] = r;
            }
            __syncthreads();
        }
        const float den2 = fmaxf(sqrtf(bres2[0] + sp[l*SPSTR+2]*sp[l*SPSTR+2]), 1e-12f);
        const float den3 = fmaxf(sqrtf(bres2[1] + sp[l*SPSTR+3]*sp[l*SPSTR+3]), 1e-12f);
        const float den4 = fmaxf(sqrtf(bres2[2] + sp[l*SPSTR+4]*sp[l*SPSTR+4]), 1e-12f);
        const float den5 = fmaxf(sqrtf(bres2[3] + sp[l*SPSTR+5]*sp[l*SPSTR+5]), 1e-12f);

        // stage-2 pass 2: sl1 / focal / liou over selected rows
        float lsl1 = 0.f, lfl = 0.f, lll = 0.f;
        const int tgt = (p1 > p0) ? 1 : 0;
        if (tid < k) {
            const float* row = feat + (size_t)sel[tid] * N_FEAT;
            float sacc = 0.f, dd, ad;
            dd = row[2] / den2 - sp[l*SPSTR+2] / den2; ad = fabsf(dd);
            sacc += (ad < 1.f) ? 0.5f * dd * dd : ad - 0.5f;
            dd = row[3] / den3 - sp[l*SPSTR+3] / den3; ad = fabsf(dd);
            sacc += (ad < 1.f) ? 0.5f * dd * dd : ad - 0.5f;
            dd = row[4] / den4 - sp[l*SPSTR+4] / den4; ad = fabsf(dd);
            sacc += (ad < 1.f) ? 0.5f * dd * dd : ad - 0.5f;
            dd = row[5] / den5 - sp[l*SPSTR+5] / den5; ad = fabsf(dd);
            sacc += (ad < 1.f) ? 0.5f * dd * dd : ad - 0.5f;
            lsl1 = sacc * 0.25f;
            float x0 = row[0], x1 = row[1];
            float mx = fmaxf(x0, x1);
            float lse = mx + logf(expf(x0 - mx) + expf(x1 - mx));
            float logpt = (tgt ? x1 : x0) - lse;
            float pt = expf(logpt);
            lfl = -(1.f - pt) * (1.f - pt) * logpt;
            float L = 0.f;
            #pragma unroll 12
            for (int j = 6; j < 78; ++j) L += fabsf(row[j] - sp[l*SPSTR+j]);
            lll = 1.f - (2160.f - L) / (2160.f + L + 1e-9f);
        }
        {
            float v;
            v = wsum(lsl1); if (lane == 0) wred[0 * 8 + wid] = v;
            v = wsum(lll);  if (lane == 0) wred[1 * 8 + wid] = v;
            v = wsum(lfl);  if (lane == 0) wred[2 * 8 + wid] = v;
            __syncthreads();
            if (tid == 0) {
                float ra = 0.f, rb = 0.f, rc = 0.f;
                for (int w = 0; w < 8; ++w) {
                    ra += wred[0 * 8 + w]; rb += wred[1 * 8 + w]; rc += wred[2 * 8 + w];
                }
                float invk = 1.f / (float)k;
                int task = img * 16 + lane0 + l;
                g_part[task * 3 + 0] = ra * invk;
                g_part[task * 3 + 1] = rb * invk;
                g_part[task * 3 + 2] = rc * invk;
            }
            __syncthreads();
        }
    }

    // ---------------- last-CTA final fold (replaces second kernel)
    if (tid == 0) {
        __threadfence();
        unsigned v = atomicAdd(&g_ctr, 1u);
        sAm = (v == NCTA - 1) ? 1u : 0u;
    }
    __syncthreads();
    if (sAm) {
        if (tid == 0) g_ctr = 0;
        __threadfence();
        float a = 0.f, b = 0.f, c = 0.f;
        for (int i = tid; i < 1024; i += NT) {
            a += g_part[i * 3 + 0];
            b += g_part[i * 3 + 1];
            c += g_part[i * 3 + 2];
        }
        float v;
        v = wsum(a); if (lane == 0) wred[0 * 8 + wid] = v;
        v = wsum(b); if (lane == 0) wred[1 * 8 + wid] = v;
        v = wsum(c); if (lane == 0) wred[2 * 8 + wid] = v;
        __syncthreads();
        if (tid == 0) {
            float sa = 0.f, sb = 0.f, sc = 0.f;
            for (int w = 0; w < 8; ++w) {
                sa += wred[0 * 8 + w]; sb += wred[1 * 8 + w]; sc += wred[2 * 8 + w];
            }
            const float inv = 1.f / 1024.f;
            float sl1l = sa * inv, ll = sb * inv, fl = sc * inv;
            out[0] = (sl1l > 0.f ? 0.5f * sl1l : 0.f)
                   + (ll   > 0.f ? 2.0f * ll   : 0.f)
                   + (fl   > 0.f ? 2.0f * fl   : 0.f);
        }
    }
}

extern "C" void kernel_launch(void* const* d_in, const int* in_sizes, int n_in,
                              void* d_out, int out_size)
{
    const float* output = (const float*)d_in[0];  // [64,1000,78]
    const float* label  = (const float*)d_in[1];  // [64,16,78]
    static bool attr_done = false;
    if (!attr_done) {
        cudaFuncSetAttribute(lane_kernel,
                             cudaFuncAttributeMaxDynamicSharedMemorySize,
                             DYN_FLOATS * sizeof(float));
        attr_done = true;
    }
    lane_kernel<<<NCTA, NT, DYN_FLOATS * sizeof(float)>>>(output, label, (float*)d_out);
}